// round 2
// baseline (speedup 1.0000x reference)
#include <cuda_runtime.h>
#include <math.h>

// ISDALoss_EM on GB300.
// Inputs (metadata order): features[N,128] f32, weight[C,128] f32, bias[C] f32,
//   pi[C,K] f32 (UNUSED - see analysis), mu[C,K,128] f32, sigma[C,K,128,128] f32,
//   labels[N] int64-or-int32, ratio scalar f32.
// Output: [loss (1 elem), y (N*C elems)] f32.

#define A_DIM 128
#define MAX_S 512
#define MAX_N 4096

// ---------------- scratch (device globals; no allocations allowed) ----------
__device__ float g_LT[(size_t)MAX_S * A_DIM * A_DIM]; // LT[s][j][i] = L[i][j], zeros above diag
__device__ float g_rdiag[MAX_S * A_DIM];              // 1 / L[j][j]
__device__ float g_logdet[MAX_S];                     // log|Sigma_s|
__device__ float g_D[MAX_S * A_DIM];                  // D[s][c] = w_c^T Sigma_s w_c   (stride 128)
__device__ float g_U[MAX_S * A_DIM];                  // U[s][c] = w_c^T Sigma_s w_cl
__device__ int   g_labels[MAX_N];
__device__ int   g_kstar[MAX_N];

// ---------------- init loss slot --------------------------------------------
__global__ void k_init(float* out, int writeLoss) {
    if (writeLoss && threadIdx.x == 0 && blockIdx.x == 0) out[0] = 0.0f;
}

// ---------------- label dtype detection + conversion ------------------------
// If labels are int64, the odd int32 words (high halves) of the first N int32
// slots are all zero. If int32, they are random labels in [0,100) -> ~never all 0.
__global__ void k_labels(const int* __restrict__ raw, int n) {
    __shared__ int odd_nz;
    if (threadIdx.x == 0) odd_nz = 0;
    __syncthreads();
    for (int i = threadIdx.x; i < n / 2; i += blockDim.x)
        if (raw[2 * i + 1] != 0) atomicOr(&odd_nz, 1);
    __syncthreads();
    if (odd_nz == 0) {
        for (int i = threadIdx.x; i < n; i += blockDim.x) g_labels[i] = raw[2 * i];
    } else {
        for (int i = threadIdx.x; i < n; i += blockDim.x) g_labels[i] = raw[i];
    }
}

// ---------------- Cholesky of each Sigma_s (128x128, SPD) -------------------
// One block of 128 threads per sigma. In-shared right-looking factorization,
// pitch 129 to keep row accesses conflict-free.
__global__ void k_chol(const float* __restrict__ sigma) {
    extern __shared__ float sA[];            // 128 x 129
    __shared__ float scol[A_DIM];
    __shared__ float red[4];
    const int s = blockIdx.x;
    const int tid = threadIdx.x;             // 0..127
    const float* src = sigma + (size_t)s * A_DIM * A_DIM;

    for (int idx = tid; idx < A_DIM * A_DIM; idx += A_DIM) {
        int r = idx >> 7, c = idx & 127;
        sA[r * 129 + c] = src[idx];
    }
    __syncthreads();

    for (int j = 0; j < A_DIM; ++j) {
        if (tid == j) sA[j * 129 + j] = sqrtf(sA[j * 129 + j]);
        __syncthreads();
        float Ljj = sA[j * 129 + j];
        float inv = 1.0f / Ljj;
        float lij = 0.0f;
        if (tid > j) {
            lij = sA[tid * 129 + j] * inv;
            sA[tid * 129 + j] = lij;
        }
        scol[tid] = lij;
        __syncthreads();
        if (tid > j) {
            // rank-1 update of this thread's row, cols (j, tid]
            for (int p = j + 1; p <= tid; ++p)
                sA[tid * 129 + p] -= lij * scol[p];
        }
        __syncthreads();
    }

    // write L^T (column-major L) with zeros above the diagonal; coalesced
    for (int j = 0; j < A_DIM; ++j) {
        float v = (tid >= j) ? sA[tid * 129 + j] : 0.0f;
        g_LT[(size_t)s * (A_DIM * A_DIM) + j * A_DIM + tid] = v;
    }
    float dg = sA[tid * 129 + tid];
    g_rdiag[s * A_DIM + tid] = 1.0f / dg;

    float v = logf(dg);
    #pragma unroll
    for (int o = 16; o; o >>= 1) v += __shfl_xor_sync(0xffffffffu, v, o);
    if ((tid & 31) == 0) red[tid >> 5] = v;
    __syncthreads();
    if (tid == 0) g_logdet[s] = 2.0f * (red[0] + red[1] + red[2] + red[3]);
}

// ---------------- per-sigma D[s,c], U[s,c] precompute ------------------------
// Block per s (128 threads, thread = row a). v_i = Sigma_s @ w_{c0+i} computed
// for 4 columns at once; Sigma read transposed (symmetric) for conflict-free LDS.
__global__ void k_du(const float* __restrict__ sigma, const float* __restrict__ W,
                     int C, int K) {
    extern __shared__ float sS[];            // 128*128, sS[b*128+a] = Sigma[b][a]
    __shared__ float swl[A_DIM];
    __shared__ __align__(16) float swc[4][A_DIM];
    __shared__ float rbuf[4][8];
    const int s = blockIdx.x;
    const int tid = threadIdx.x;             // 0..127
    const int cl = s / K;
    const int a = tid;
    const int warp = tid >> 5, lane = tid & 31;
    const float* src = sigma + (size_t)s * A_DIM * A_DIM;

    for (int idx = tid; idx < A_DIM * A_DIM; idx += A_DIM) sS[idx] = src[idx];
    swl[tid] = W[cl * A_DIM + tid];
    __syncthreads();

    for (int c0 = 0; c0 < C; c0 += 4) {
        for (int idx = tid; idx < 4 * A_DIM; idx += A_DIM) {
            int ci = idx >> 7, b = idx & 127;
            int c = c0 + ci;
            swc[ci][b] = (c < C) ? W[c * A_DIM + b] : 0.0f;
        }
        __syncthreads();

        float acc0 = 0.f, acc1 = 0.f, acc2 = 0.f, acc3 = 0.f;
        #pragma unroll 8
        for (int b = 0; b < A_DIM; b += 4) {
            float4 w0 = *reinterpret_cast<const float4*>(&swc[0][b]);
            float4 w1 = *reinterpret_cast<const float4*>(&swc[1][b]);
            float4 w2 = *reinterpret_cast<const float4*>(&swc[2][b]);
            float4 w3 = *reinterpret_cast<const float4*>(&swc[3][b]);
            float sv0 = sS[(b + 0) * A_DIM + a];
            float sv1 = sS[(b + 1) * A_DIM + a];
            float sv2 = sS[(b + 2) * A_DIM + a];
            float sv3 = sS[(b + 3) * A_DIM + a];
            acc0 += sv0 * w0.x + sv1 * w0.y + sv2 * w0.z + sv3 * w0.w;
            acc1 += sv0 * w1.x + sv1 * w1.y + sv2 * w1.z + sv3 * w1.w;
            acc2 += sv0 * w2.x + sv1 * w2.y + sv2 * w2.z + sv3 * w2.w;
            acc3 += sv0 * w3.x + sv1 * w3.y + sv2 * w3.z + sv3 * w3.w;
        }
        // acc_i[a] = (Sigma w_{c0+i})[a]
        float wl = swl[a];
        float vals[8] = { acc0 * swc[0][a], acc1 * swc[1][a],
                          acc2 * swc[2][a], acc3 * swc[3][a],
                          acc0 * wl, acc1 * wl, acc2 * wl, acc3 * wl };
        #pragma unroll
        for (int v = 0; v < 8; ++v) {
            float x = vals[v];
            #pragma unroll
            for (int o = 16; o; o >>= 1) x += __shfl_xor_sync(0xffffffffu, x, o);
            if (lane == 0) rbuf[warp][v] = x;
        }
        __syncthreads();
        if (tid < 8) {
            float t = rbuf[0][tid] + rbuf[1][tid] + rbuf[2][tid] + rbuf[3][tid];
            int ci = tid & 3;
            int c = c0 + ci;
            if (c < C) {
                if (tid < 4) g_D[s * A_DIM + c] = t;
                else         g_U[s * A_DIM + c] = t;
            }
        }
        __syncthreads();
    }
}

// ---------------- expect: k*(n) = argmin_k (dist + logdet) ------------------
// One block per n, one warp per k. Forward solve L z = diff with lane r owning
// rows 4r..4r+3 (float4 coalesced column loads from L^T).
__global__ void k_expect(const float* __restrict__ F, const float* __restrict__ mu,
                         int N, int K) {
    const int n = blockIdx.x;
    const int warp = threadIdx.x >> 5, lane = threadIdx.x & 31;
    __shared__ float sscore[8];
    const int l = g_labels[n];

    if (warp < K) {
        const int s = l * K + warp;
        const float* LT = g_LT + (size_t)s * (A_DIM * A_DIM);
        const float* rd = g_rdiag + s * A_DIM;
        float4 fv = *reinterpret_cast<const float4*>(F + (size_t)n * A_DIM + 4 * lane);
        float4 mv = *reinterpret_cast<const float4*>(mu + (size_t)s * A_DIM + 4 * lane);
        float d0 = fv.x - mv.x, d1 = fv.y - mv.y, d2 = fv.z - mv.z, d3 = fv.w - mv.w;
        float dist = 0.0f;
        #pragma unroll 4
        for (int j = 0; j < A_DIM; ++j) {
            float4 col = make_float4(0.f, 0.f, 0.f, 0.f);
            if (4 * lane + 3 >= j)   // lower-triangle rows only (above-diag is 0 anyway)
                col = *reinterpret_cast<const float4*>(LT + j * A_DIM + 4 * lane);
            int owner = j >> 2, q = j & 3;
            float dq = (q == 0) ? d0 : (q == 1) ? d1 : (q == 2) ? d2 : d3;
            float dj = __shfl_sync(0xffffffffu, dq, owner);
            float zj = dj * rd[j];
            dist += zj * zj;
            d0 -= col.x * zj;
            d1 -= col.y * zj;
            d2 -= col.z * zj;
            d3 -= col.w * zj;
        }
        if (lane == 0) sscore[warp] = dist + g_logdet[s];
    }
    __syncthreads();
    if (threadIdx.x == 0) {
        float best = sscore[0];
        int bk = 0;
        for (int k = 1; k < K; ++k)
            if (sscore[k] < best) { best = sscore[k]; bk = k; }   // first-min tie-break
        g_kstar[n] = bk;
    }
}

// ---------------- fused y = F W^T + b, aug, log-softmax, loss ----------------
__global__ void k_yloss(const float* __restrict__ F, const float* __restrict__ W,
                        const float* __restrict__ bias, const float* __restrict__ ratioPtr,
                        float* __restrict__ yout, float* __restrict__ lossout,
                        int N, int C, int K, int writeLoss) {
    extern __shared__ float sh[];
    const int NB = 16;
    float* sWT = sh;                    // [128][C]  (W transposed)
    float* sF  = sWT + A_DIM * C;       // [NB][128]
    float* sY  = sF + NB * A_DIM;       // [NB][C]
    float* sB  = sY + NB * C;           // [C]
    const int tid = threadIdx.x;        // 256 threads
    const int n0 = blockIdx.x * NB;

    for (int idx = tid; idx < C * A_DIM; idx += 256) {
        int c = idx >> 7, aa = idx & 127;
        sWT[aa * C + c] = W[idx];
    }
    for (int idx = tid; idx < NB * A_DIM; idx += 256) {
        int nl = idx >> 7;
        int n = n0 + nl;
        sF[idx] = (n < N) ? F[(size_t)n * A_DIM + (idx & 127)] : 0.0f;
    }
    for (int c = tid; c < C; c += 256) sB[c] = bias[c];
    __syncthreads();

    const int warp = tid >> 5, lane = tid & 31;
    const int nchunk = (C + 31) >> 5;

    for (int task = warp; task < NB * nchunk; task += 8) {
        int nl = task / nchunk;
        int c = (task - nl * nchunk) * 32 + lane;
        int n = n0 + nl;
        if (c < C && n < N) {
            float acc = sB[c];
            const float* f = sF + nl * A_DIM;
            #pragma unroll 8
            for (int aa = 0; aa < A_DIM; ++aa) acc += f[aa] * sWT[aa * C + c];
            sY[nl * C + c] = acc;
            yout[(size_t)n * C + c] = acc;
        }
    }
    __syncthreads();

    const float hr = 0.5f * ratioPtr[0];
    for (int nl = warp; nl < NB; nl += 8) {
        int n = n0 + nl;
        if (n >= N) continue;
        int l = g_labels[n];
        int k = g_kstar[n];
        int s = l * K + k;
        const float* Dp = g_D + s * A_DIM;
        const float* Up = g_U + s * A_DIM;
        float ul = Up[l];
        float mymax = -INFINITY;
        float augv[8];
        for (int m = 0; m < nchunk; ++m) {
            int c = lane + 32 * m;
            float v = -INFINITY;
            if (c < C) v = sY[nl * C + c] + hr * (Dp[c] - 2.0f * Up[c] + ul);
            augv[m] = v;
            mymax = fmaxf(mymax, v);
        }
        #pragma unroll
        for (int o = 16; o; o >>= 1) mymax = fmaxf(mymax, __shfl_xor_sync(0xffffffffu, mymax, o));
        float sum = 0.0f;
        for (int m = 0; m < nchunk; ++m) {
            int c = lane + 32 * m;
            if (c < C) sum += expf(augv[m] - mymax);
        }
        #pragma unroll
        for (int o = 16; o; o >>= 1) sum += __shfl_xor_sync(0xffffffffu, sum, o);
        if (lane == 0 && writeLoss) {
            float lse = mymax + logf(sum);
            float aug_l = sY[nl * C + l] + hr * (Dp[l] - Up[l]); // -2u_l + u_l = -u_l
            atomicAdd(lossout, (lse - aug_l) / (float)N);
        }
    }
}

// ---------------- launch -----------------------------------------------------
extern "C" void kernel_launch(void* const* d_in, const int* in_sizes, int n_in,
                              void* d_out, int out_size) {
    const float* F      = (const float*)d_in[0];
    const float* W      = (const float*)d_in[1];
    const float* bias   = (const float*)d_in[2];
    /* d_in[3] = pi : unused (argmax(q) == argmax(log_p)) */
    const float* mu     = (const float*)d_in[4];
    const float* sigma  = (const float*)d_in[5];
    const int*   lraw   = (const int*)d_in[6];
    const float* ratio  = (const float*)d_in[7];

    const int C = in_sizes[2];                 // 100
    const int K = in_sizes[3] / C;             // 4
    const int Ad = in_sizes[1] / C;            // 128 (design assumes 128)
    const int N = in_sizes[0] / Ad;            // 2048
    const int S = C * K;                       // 400

    float* out = (float*)d_out;
    const int yoff = out_size - N * C;         // expected 1 (loss slot first)
    const int writeLoss = (yoff >= 1) ? 1 : 0;
    float* yout = out + (yoff > 0 ? yoff : 0);

    const int smem_chol = A_DIM * 129 * 4;                     // 66048
    const int smem_du   = A_DIM * A_DIM * 4;                   // 65536
    const int smem_yl   = (A_DIM * C + 16 * A_DIM + 16 * C + C) * 4;

    cudaFuncSetAttribute(k_chol,  cudaFuncAttributeMaxDynamicSharedMemorySize, smem_chol);
    cudaFuncSetAttribute(k_du,    cudaFuncAttributeMaxDynamicSharedMemorySize, smem_du);
    cudaFuncSetAttribute(k_yloss, cudaFuncAttributeMaxDynamicSharedMemorySize, smem_yl);

    k_init<<<1, 32>>>(out, writeLoss);
    k_labels<<<1, 256>>>(lraw, N);
    k_chol<<<S, A_DIM, smem_chol>>>(sigma);
    k_du<<<S, A_DIM, smem_du>>>(sigma, W, C, K);
    k_expect<<<N, 32 * K>>>(F, mu, N, K);
    k_yloss<<<(N + 15) / 16, 256, smem_yl>>>(F, W, bias, ratio, yout, out, N, C, K, writeLoss);
}

// round 3
// speedup vs baseline: 2.3705x; 2.3705x over previous
#include <cuda_runtime.h>
#include <math.h>

// ISDALoss_EM on GB300 — fused blocked-Cholesky + D/U kernel.
#define A_DIM 128
#define PITCH 132
#define MAX_S 512
#define MAX_N 4096

__device__ float g_LT[(size_t)MAX_S * A_DIM * A_DIM];
__device__ float g_rdiag[MAX_S * A_DIM];
__device__ float g_logdet[MAX_S];
__device__ float g_D[MAX_S * A_DIM];
__device__ float g_U[MAX_S * A_DIM];
__device__ int   g_labels[MAX_N];
__device__ int   g_kstar[MAX_N];

__device__ __forceinline__ void fma2(unsigned long long& d, unsigned long long a,
                                     unsigned long long b) {
    asm("fma.rn.f32x2 %0, %1, %2, %0;" : "+l"(d) : "l"(a), "l"(b));
}
__device__ __forceinline__ unsigned long long pack2(float lo, float hi) {
    unsigned long long r;
    asm("mov.b64 %0, {%1,%2};" : "=l"(r) : "f"(lo), "f"(hi));
    return r;
}
__device__ __forceinline__ float2 unpack2(unsigned long long v) {
    float2 f;
    asm("mov.b64 {%0,%1}, %2;" : "=f"(f.x), "=f"(f.y) : "l"(v));
    return f;
}

__global__ void k_init(float* out, int writeLoss) {
    if (writeLoss && threadIdx.x == 0 && blockIdx.x == 0) out[0] = 0.0f;
}

__global__ void k_labels(const int* __restrict__ raw, int n) {
    __shared__ int odd_nz;
    if (threadIdx.x == 0) odd_nz = 0;
    __syncthreads();
    for (int i = threadIdx.x; i < n / 2; i += blockDim.x)
        if (raw[2 * i + 1] != 0) atomicOr(&odd_nz, 1);
    __syncthreads();
    if (odd_nz == 0) {
        for (int i = threadIdx.x; i < n; i += blockDim.x) g_labels[i] = raw[2 * i];
    } else {
        for (int i = threadIdx.x; i < n; i += blockDim.x) g_labels[i] = raw[i];
    }
}

// ---------------- fused: D/U (from Sigma) + blocked Cholesky ------------------
__global__ __launch_bounds__(256, 2)
void k_fused(const float* __restrict__ sigma, const float* __restrict__ W,
             int C, int K) {
    extern __shared__ float sh[];
    float* sA  = sh;                       // 128 * 132
    float* sWc = sA + A_DIM * PITCH;       // 32 cols * 128
    float* swl = sWc + 32 * A_DIM;         // 128
    float* sv  = swl + A_DIM;              // 128
    float* srd = sv + A_DIM;               // 128
    float* sdg = srd + A_DIM;              // 128

    const int s = blockIdx.x;
    const int cls = s / K;
    const int tid = threadIdx.x;
    const int wid = tid >> 5, lane = tid & 31;

    // load Sigma (float4, coalesced) into pitched shared
    {
        const float4* src4 = reinterpret_cast<const float4*>(sigma + (size_t)s * A_DIM * A_DIM);
        for (int idx = tid; idx < A_DIM * 32; idx += 256) {
            int i = idx >> 5, f = idx & 31;
            *reinterpret_cast<float4*>(&sA[i * PITCH + 4 * f]) = src4[idx];
        }
        if (tid < A_DIM) swl[tid] = W[cls * A_DIM + tid];
    }
    __syncthreads();

    // v = Sigma @ w_l  (symmetric -> column reads, conflict-free)
    if (tid < A_DIM) {
        float acc = 0.0f;
        #pragma unroll 8
        for (int b = 0; b < A_DIM; ++b) acc += sA[b * PITCH + tid] * swl[b];
        sv[tid] = acc;
    }

    // ---- D[c] = w_c^T Sigma w_c,  U[c] = v . w_c, chunks of 32 columns ----
    for (int c0 = 0; c0 < C; c0 += 32) {
        __syncthreads();
        for (int idx = tid; idx < 32 * 32; idx += 256) {
            int cc = idx >> 5, f = idx & 31;
            int c = c0 + cc;
            float4 wv = (c < C) ? reinterpret_cast<const float4*>(W + (size_t)c * A_DIM)[f]
                                : make_float4(0.f, 0.f, 0.f, 0.f);
            *reinterpret_cast<float4*>(&sWc[cc * A_DIM + 4 * f]) = wv;
        }
        __syncthreads();

        const int q0 = 4 * wid;
        unsigned long long a01[4] = {0ull, 0ull, 0ull, 0ull};
        unsigned long long a23[4] = {0ull, 0ull, 0ull, 0ull};
        const float* pA = sA + 4 * lane;
        #pragma unroll 4
        for (int b = 0; b < A_DIM; ++b) {
            ulonglong2 sg = *reinterpret_cast<const ulonglong2*>(pA + b * PITCH);
            #pragma unroll
            for (int q = 0; q < 4; ++q) {
                float wv = sWc[(q0 + q) * A_DIM + b];
                unsigned long long w2 = pack2(wv, wv);
                fma2(a01[q], sg.x, w2);
                fma2(a23[q], sg.y, w2);
            }
        }
        float4 v4 = *reinterpret_cast<const float4*>(&sv[4 * lane]);
        #pragma unroll
        for (int q = 0; q < 4; ++q) {
            int c = c0 + q0 + q;
            float4 wq = *reinterpret_cast<const float4*>(&sWc[(q0 + q) * A_DIM + 4 * lane]);
            float2 f01 = unpack2(a01[q]), f23 = unpack2(a23[q]);
            float dpart = f01.x * wq.x + f01.y * wq.y + f23.x * wq.z + f23.y * wq.w;
            float upart = v4.x * wq.x + v4.y * wq.y + v4.z * wq.z + v4.w * wq.w;
            #pragma unroll
            for (int o = 16; o; o >>= 1) {
                dpart += __shfl_xor_sync(0xffffffffu, dpart, o);
                upart += __shfl_xor_sync(0xffffffffu, upart, o);
            }
            if (lane == 0 && c < C) {
                g_D[s * A_DIM + c] = dpart;
                g_U[s * A_DIM + c] = upart;
            }
        }
    }
    __syncthreads();

    // ---- blocked Cholesky (NB = 32) ----
    for (int kb = 0; kb < A_DIM; kb += 32) {
        if (wid == 0) {                       // 32x32 diagonal factor in registers
            float m[32];
            float* row = &sA[(kb + lane) * PITCH + kb];
            #pragma unroll
            for (int c = 0; c < 32; ++c) m[c] = row[c];
            #pragma unroll
            for (int j = 0; j < 32; ++j) {
                float dj = __shfl_sync(0xffffffffu, m[j], j);
                float l = m[j] * rsqrtf(dj);
                m[j] = l;
                #pragma unroll
                for (int p = j + 1; p < 32; ++p)
                    m[p] -= l * __shfl_sync(0xffffffffu, l, p);
            }
            #pragma unroll
            for (int c = 0; c < 32; ++c)
                if (c <= lane) row[c] = m[c];
            srd[kb + lane] = 1.0f / m[lane];
            sdg[kb + lane] = m[lane];
        }
        __syncthreads();

        const int R = A_DIM - kb - 32;
        if (R > 0) {
            if (tid < R) {                    // panel solve: x L_d^T layout, row-owned
                const int row = kb + 32 + tid;
                float* pr = &sA[row * PITCH + kb];
                const float* pd = &sA[kb * PITCH + kb];
                float x[32];
                #pragma unroll
                for (int c = 0; c < 32; ++c) x[c] = pr[c];
                #pragma unroll
                for (int j = 0; j < 32; ++j) {
                    float a = x[j];
                    #pragma unroll
                    for (int p = 0; p < j; ++p) a -= x[p] * pd[j * PITCH + p];
                    x[j] = a * srd[kb + j];
                }
                #pragma unroll
                for (int c = 0; c < 32; ++c) pr[c] = x[c];
            }
            __syncthreads();

            const int nb = R >> 5;            // SYRK: A22 -= L21 L21^T (lower)
            const int ntask = nb * (nb + 1);
            for (int task = wid; task < ntask; task += 8) {
                int b = 0, t = task;
                while (t >= 2 * b + 2) { t -= 2 * b + 2; ++b; }
                const int i  = kb + 32 + 32 * b + lane;
                const int j0 = kb + 32 + 16 * t;
                unsigned long long acc[16];
                #pragma unroll
                for (int q = 0; q < 16; ++q) acc[q] = 0ull;
                const float* pa = &sA[i * PITCH + kb];
                #pragma unroll
                for (int k = 0; k < 32; k += 4) {
                    ulonglong2 av = *reinterpret_cast<const ulonglong2*>(pa + k);
                    #pragma unroll
                    for (int q = 0; q < 16; ++q) {
                        ulonglong2 bv = *reinterpret_cast<const ulonglong2*>(
                            &sA[(j0 + q) * PITCH + kb + k]);
                        fma2(acc[q], av.x, bv.x);
                        fma2(acc[q], av.y, bv.y);
                    }
                }
                #pragma unroll
                for (int q = 0; q < 16; ++q) {
                    int col = j0 + q;
                    if (col <= i) {
                        float2 f = unpack2(acc[q]);
                        sA[i * PITCH + col] -= f.x + f.y;
                    }
                }
            }
            __syncthreads();
        }
    }

    // ---- outputs: L^T (zero upper), rdiag, logdet ----
    {
        float* LT = g_LT + (size_t)s * (A_DIM * A_DIM);
        for (int idx = tid; idx < A_DIM * A_DIM; idx += 256) {
            int j = idx >> 7, i = idx & 127;
            LT[idx] = (i >= j) ? sA[i * PITCH + j] : 0.0f;
        }
        if (tid < A_DIM) g_rdiag[s * A_DIM + tid] = srd[tid];
        if (tid < 32) {
            float v = logf(sdg[tid]) + logf(sdg[tid + 32]) +
                      logf(sdg[tid + 64]) + logf(sdg[tid + 96]);
            #pragma unroll
            for (int o = 16; o; o >>= 1) v += __shfl_xor_sync(0xffffffffu, v, o);
            if (tid == 0) g_logdet[s] = 2.0f * v;
        }
    }
}

// ---------------- expect: k*(n) = argmin_k (dist + logdet) ------------------
__global__ void k_expect(const float* __restrict__ F, const float* __restrict__ mu,
                         int N, int K) {
    const int n = blockIdx.x;
    const int warp = threadIdx.x >> 5, lane = threadIdx.x & 31;
    __shared__ float sscore[8];
    const int l = g_labels[n];

    if (warp < K) {
        const int s = l * K + warp;
        const float* LT = g_LT + (size_t)s * (A_DIM * A_DIM);
        const float* rd = g_rdiag + s * A_DIM;
        float4 fv = *reinterpret_cast<const float4*>(F + (size_t)n * A_DIM + 4 * lane);
        float4 mv = *reinterpret_cast<const float4*>(mu + (size_t)s * A_DIM + 4 * lane);
        float d0 = fv.x - mv.x, d1 = fv.y - mv.y, d2 = fv.z - mv.z, d3 = fv.w - mv.w;
        float dist = 0.0f;
        #pragma unroll 4
        for (int j = 0; j < A_DIM; ++j) {
            float4 col = make_float4(0.f, 0.f, 0.f, 0.f);
            if (4 * lane + 3 >= j)
                col = *reinterpret_cast<const float4*>(LT + j * A_DIM + 4 * lane);
            int owner = j >> 2, q = j & 3;
            float dq = (q == 0) ? d0 : (q == 1) ? d1 : (q == 2) ? d2 : d3;
            float dj = __shfl_sync(0xffffffffu, dq, owner);
            float zj = dj * rd[j];
            dist += zj * zj;
            d0 -= col.x * zj;
            d1 -= col.y * zj;
            d2 -= col.z * zj;
            d3 -= col.w * zj;
        }
        if (lane == 0) sscore[warp] = dist + g_logdet[s];
    }
    __syncthreads();
    if (threadIdx.x == 0) {
        float best = sscore[0];
        int bk = 0;
        for (int k = 1; k < K; ++k)
            if (sscore[k] < best) { best = sscore[k]; bk = k; }
        g_kstar[n] = bk;
    }
}

// ---------------- fused y = F W^T + b, aug, log-softmax, loss ----------------
__global__ void k_yloss(const float* __restrict__ F, const float* __restrict__ W,
                        const float* __restrict__ bias, const float* __restrict__ ratioPtr,
                        float* __restrict__ yout, float* __restrict__ lossout,
                        int N, int C, int K, int writeLoss) {
    extern __shared__ float sh[];
    const int NB = 16;
    float* sWT = sh;
    float* sF  = sWT + A_DIM * C;
    float* sY  = sF + NB * A_DIM;
    float* sB  = sY + NB * C;
    const int tid = threadIdx.x;
    const int n0 = blockIdx.x * NB;

    for (int idx = tid; idx < C * A_DIM; idx += 256) {
        int c = idx >> 7, aa = idx & 127;
        sWT[aa * C + c] = W[idx];
    }
    for (int idx = tid; idx < NB * A_DIM; idx += 256) {
        int nl = idx >> 7;
        int n = n0 + nl;
        sF[idx] = (n < N) ? F[(size_t)n * A_DIM + (idx & 127)] : 0.0f;
    }
    for (int c = tid; c < C; c += 256) sB[c] = bias[c];
    __syncthreads();

    const int warp = tid >> 5, lane = tid & 31;
    const int nchunk = (C + 31) >> 5;

    for (int task = warp; task < NB * nchunk; task += 8) {
        int nl = task / nchunk;
        int c = (task - nl * nchunk) * 32 + lane;
        int n = n0 + nl;
        if (c < C && n < N) {
            float acc = sB[c];
            const float* f = sF + nl * A_DIM;
            #pragma unroll 8
            for (int aa = 0; aa < A_DIM; ++aa) acc += f[aa] * sWT[aa * C + c];
            sY[nl * C + c] = acc;
            yout[(size_t)n * C + c] = acc;
        }
    }
    __syncthreads();

    const float hr = 0.5f * ratioPtr[0];
    for (int nl = warp; nl < NB; nl += 8) {
        int n = n0 + nl;
        if (n >= N) continue;
        int l = g_labels[n];
        int k = g_kstar[n];
        int s = l * K + k;
        const float* Dp = g_D + s * A_DIM;
        const float* Up = g_U + s * A_DIM;
        float ul = Up[l];
        float mymax = -INFINITY;
        float augv[8];
        for (int m = 0; m < nchunk; ++m) {
            int c = lane + 32 * m;
            float v = -INFINITY;
            if (c < C) v = sY[nl * C + c] + hr * (Dp[c] - 2.0f * Up[c] + ul);
            augv[m] = v;
            mymax = fmaxf(mymax, v);
        }
        #pragma unroll
        for (int o = 16; o; o >>= 1) mymax = fmaxf(mymax, __shfl_xor_sync(0xffffffffu, mymax, o));
        float sum = 0.0f;
        for (int m = 0; m < nchunk; ++m) {
            int c = lane + 32 * m;
            if (c < C) sum += expf(augv[m] - mymax);
        }
        #pragma unroll
        for (int o = 16; o; o >>= 1) sum += __shfl_xor_sync(0xffffffffu, sum, o);
        if (lane == 0 && writeLoss) {
            float lse = mymax + logf(sum);
            float aug_l = sY[nl * C + l] + hr * (Dp[l] - Up[l]);
            atomicAdd(lossout, (lse - aug_l) / (float)N);
        }
    }
}

// ---------------- launch -----------------------------------------------------
extern "C" void kernel_launch(void* const* d_in, const int* in_sizes, int n_in,
                              void* d_out, int out_size) {
    const float* F     = (const float*)d_in[0];
    const float* W     = (const float*)d_in[1];
    const float* bias  = (const float*)d_in[2];
    const float* mu    = (const float*)d_in[4];
    const float* sigma = (const float*)d_in[5];
    const int*   lraw  = (const int*)d_in[6];
    const float* ratio = (const float*)d_in[7];

    const int C = in_sizes[2];
    const int K = in_sizes[3] / C;
    const int Ad = in_sizes[1] / C;
    const int N = in_sizes[0] / Ad;
    const int S = C * K;

    float* out = (float*)d_out;
    const int yoff = out_size - N * C;
    const int writeLoss = (yoff >= 1) ? 1 : 0;
    float* yout = out + (yoff > 0 ? yoff : 0);

    const int smem_fused = (A_DIM * PITCH + 32 * A_DIM + 4 * A_DIM) * 4;  // 86016
    const int smem_yl    = (A_DIM * C + 16 * A_DIM + 16 * C + C) * 4;

    cudaFuncSetAttribute(k_fused, cudaFuncAttributeMaxDynamicSharedMemorySize, smem_fused);
    cudaFuncSetAttribute(k_yloss, cudaFuncAttributeMaxDynamicSharedMemorySize, smem_yl);

    k_init<<<1, 32>>>(out, writeLoss);
    k_labels<<<1, 256>>>(lraw, N);
    k_fused<<<S, 256, smem_fused>>>(sigma, W, C, K);
    k_expect<<<N, 32 * K>>>(F, mu, N, K);
    k_yloss<<<(N + 15) / 16, 256, smem_yl>>>(F, W, bias, ratio, yout, out, N, C, K, writeLoss);
}

// round 4
// speedup vs baseline: 2.6447x; 1.1157x over previous
#include <cuda_runtime.h>
#include <math.h>

// ISDALoss_EM on GB300 — round 4.
#define A_DIM 128
#define PITCH 132
#define MAX_S 512
#define MAX_N 4096
#define MAX_C 128

__device__ float g_LT[(size_t)MAX_S * A_DIM * A_DIM]; // LT[s][j][i] = L[i][j], zero above diag
__device__ float g_rdiag[MAX_S * A_DIM];
__device__ float g_logdet[MAX_S];
__device__ float g_D[MAX_S * A_DIM];
__device__ float g_U[MAX_S * A_DIM];
__device__ float g_score[MAX_N * 8];
__device__ int   g_labels[MAX_N];
__device__ int   g_ccount[MAX_C];
__device__ int   g_clist[(size_t)MAX_C * MAX_N];

__device__ __forceinline__ void fma2(unsigned long long& d, unsigned long long a,
                                     unsigned long long b) {
    asm("fma.rn.f32x2 %0, %1, %2, %0;" : "+l"(d) : "l"(a), "l"(b));
}
__device__ __forceinline__ unsigned long long pack2(float lo, float hi) {
    unsigned long long r;
    asm("mov.b64 %0, {%1,%2};" : "=l"(r) : "f"(lo), "f"(hi));
    return r;
}
__device__ __forceinline__ float2 unpack2(unsigned long long v) {
    float2 f;
    asm("mov.b64 {%0,%1}, %2;" : "=f"(f.x), "=f"(f.y) : "l"(v));
    return f;
}

__global__ void k_init(float* out, int writeLoss) {
    if (writeLoss && threadIdx.x == 0 && blockIdx.x == 0) out[0] = 0.0f;
}

// labels: dtype detect + convert + per-class sample lists (single block)
__global__ void k_labels(const int* __restrict__ raw, int n, int C) {
    __shared__ int odd_nz;
    const int tid = threadIdx.x;
    if (tid == 0) odd_nz = 0;
    if (tid < MAX_C) g_ccount[tid] = 0;
    __syncthreads();
    for (int i = tid; i < n / 2; i += blockDim.x)
        if (raw[2 * i + 1] != 0) atomicOr(&odd_nz, 1);
    __syncthreads();
    if (odd_nz == 0) {
        for (int i = tid; i < n; i += blockDim.x) g_labels[i] = raw[2 * i];
    } else {
        for (int i = tid; i < n; i += blockDim.x) g_labels[i] = raw[i];
    }
    __syncthreads();
    for (int i = tid; i < n; i += blockDim.x) {
        int c = g_labels[i];
        int p = atomicAdd(&g_ccount[c], 1);
        g_clist[(size_t)c * MAX_N + p] = i;
    }
}

// ---------------- fused: v, blocked Cholesky, LT out, D/U via L^T W^T --------
__global__ __launch_bounds__(256, 2)
void k_fused(const float* __restrict__ sigma, const float* __restrict__ W,
             int C, int K) {
    extern __shared__ float sh[];
    float* sA  = sh;                       // 128 * 132
    float* sW  = sA + A_DIM * PITCH;       // 128 * 33   (w[i][cc] for current 32-col group)
    float* swl = sW + A_DIM * 33;          // 128
    float* sv  = swl + A_DIM;              // 128
    float* srd = sv + A_DIM;               // 128
    float* sdg = srd + A_DIM;              // 128
    float* sD  = sdg + A_DIM;              // 128
    float* sU  = sD + A_DIM;               // 128

    const int s = blockIdx.x;
    const int cls = s / K;
    const int tid = threadIdx.x;
    const int wid = tid >> 5, lane = tid & 31;

    // load Sigma (float4, coalesced), w_l; zero sD
    {
        const float4* src4 = reinterpret_cast<const float4*>(sigma + (size_t)s * A_DIM * A_DIM);
        for (int idx = tid; idx < A_DIM * 32; idx += 256) {
            int i = idx >> 5, f = idx & 31;
            *reinterpret_cast<float4*>(&sA[i * PITCH + 4 * f]) = src4[idx];
        }
        if (tid < A_DIM) { swl[tid] = W[cls * A_DIM + tid]; sD[tid] = 0.0f; }
    }
    __syncthreads();

    // v = Sigma @ w_l (before factorization overwrites the lower triangle)
    if (tid < A_DIM) {
        float acc = 0.0f;
        #pragma unroll 8
        for (int b = 0; b < A_DIM; ++b) acc += sA[b * PITCH + tid] * swl[b];
        sv[tid] = acc;
    }
    __syncthreads();

    // ---- blocked Cholesky (NB = 32) ----
    for (int kb = 0; kb < A_DIM; kb += 32) {
        if (wid == 0) {
            float m[32];
            float* row = &sA[(kb + lane) * PITCH + kb];
            #pragma unroll
            for (int c = 0; c < 32; ++c) m[c] = row[c];
            #pragma unroll
            for (int j = 0; j < 32; ++j) {
                float dj = __shfl_sync(0xffffffffu, m[j], j);
                float l = m[j] * rsqrtf(dj);
                m[j] = l;
                #pragma unroll
                for (int p = j + 1; p < 32; ++p)
                    m[p] -= l * __shfl_sync(0xffffffffu, l, p);
            }
            #pragma unroll
            for (int c = 0; c < 32; ++c)
                if (c <= lane) row[c] = m[c];
            srd[kb + lane] = 1.0f / m[lane];
            sdg[kb + lane] = m[lane];
        }
        __syncthreads();

        const int R = A_DIM - kb - 32;
        if (R > 0) {
            if (tid < R) {
                const int row = kb + 32 + tid;
                float* pr = &sA[row * PITCH + kb];
                const float* pd = &sA[kb * PITCH + kb];
                float x[32];
                #pragma unroll
                for (int c = 0; c < 32; ++c) x[c] = pr[c];
                #pragma unroll
                for (int j = 0; j < 32; ++j) {
                    float a = x[j];
                    #pragma unroll
                    for (int p = 0; p < j; ++p) a -= x[p] * pd[j * PITCH + p];
                    x[j] = a * srd[kb + j];
                }
                #pragma unroll
                for (int c = 0; c < 32; ++c) pr[c] = x[c];
            }
            __syncthreads();

            const int nb = R >> 5;
            const int ntask = nb * (nb + 1);
            for (int task = wid; task < ntask; task += 8) {
                int b = 0, t = task;
                while (t >= 2 * b + 2) { t -= 2 * b + 2; ++b; }
                const int i  = kb + 32 + 32 * b + lane;
                const int j0 = kb + 32 + 16 * t;
                unsigned long long acc[16];
                #pragma unroll
                for (int q = 0; q < 16; ++q) acc[q] = 0ull;
                const float* pa = &sA[i * PITCH + kb];
                #pragma unroll
                for (int k = 0; k < 32; k += 4) {
                    ulonglong2 av = *reinterpret_cast<const ulonglong2*>(pa + k);
                    #pragma unroll
                    for (int q = 0; q < 16; ++q) {
                        ulonglong2 bv = *reinterpret_cast<const ulonglong2*>(
                            &sA[(j0 + q) * PITCH + kb + k]);
                        fma2(acc[q], av.x, bv.x);
                        fma2(acc[q], av.y, bv.y);
                    }
                }
                #pragma unroll
                for (int q = 0; q < 16; ++q) {
                    int col = j0 + q;
                    if (col <= i) {
                        float2 f = unpack2(acc[q]);
                        sA[i * PITCH + col] -= f.x + f.y;
                    }
                }
            }
            __syncthreads();
        }
    }

    // ---- write LT (zero upper), zero sA's upper triangle, rdiag, logdet ----
    {
        float* LT = g_LT + (size_t)s * (A_DIM * A_DIM);
        for (int idx = tid; idx < A_DIM * A_DIM; idx += 256) {
            int j = idx >> 7, i = idx & 127;
            if (i >= j) {
                LT[idx] = sA[i * PITCH + j];
            } else {
                LT[idx] = 0.0f;
                sA[i * PITCH + j] = 0.0f;
            }
        }
        if (tid < A_DIM) g_rdiag[s * A_DIM + tid] = srd[tid];
        if (tid < 32) {
            float v = logf(sdg[tid]) + logf(sdg[tid + 32]) +
                      logf(sdg[tid + 64]) + logf(sdg[tid + 96]);
            #pragma unroll
            for (int o = 16; o; o >>= 1) v += __shfl_xor_sync(0xffffffffu, v, o);
            if (tid == 0) g_logdet[s] = 2.0f * v;
        }
    }

    // ---- D_c = ||L^T w_c||^2 (triangular, register-tiled), U_c = v . w_c ----
    for (int g = 0; g < 4; ++g) {
        __syncthreads();
        // stage w for columns c = 32g .. 32g+31 as sW[i][cc]
        for (int idx = tid; idx < 32 * 32; idx += 256) {
            int cc = idx >> 5, f = idx & 31;
            int c = 32 * g + cc;
            float4 wv = (c < C) ? reinterpret_cast<const float4*>(W + (size_t)c * A_DIM)[f]
                                : make_float4(0.f, 0.f, 0.f, 0.f);
            sW[(4 * f + 0) * 33 + cc] = wv.x;
            sW[(4 * f + 1) * 33 + cc] = wv.y;
            sW[(4 * f + 2) * 33 + cc] = wv.z;
            sW[(4 * f + 3) * 33 + cc] = wv.w;
        }
        __syncthreads();

        const int t = (g & 1) ? (7 - wid) : wid;   // load-balance across groups
        const int j0 = 16 * t;
        unsigned long long acc[8];
        #pragma unroll
        for (int q = 0; q < 8; ++q) acc[q] = 0ull;
        float u = 0.0f;
        const bool doU = (t == 0);

        for (int i = j0; i < A_DIM; ++i) {
            const float* Lr = &sA[i * PITCH + j0];
            float4 L0 = *reinterpret_cast<const float4*>(Lr);
            float4 L1 = *reinterpret_cast<const float4*>(Lr + 4);
            float4 L2 = *reinterpret_cast<const float4*>(Lr + 8);
            float4 L3 = *reinterpret_cast<const float4*>(Lr + 12);
            float wv = sW[i * 33 + lane];
            unsigned long long w2 = pack2(wv, wv);
            fma2(acc[0], pack2(L0.x, L0.y), w2);
            fma2(acc[1], pack2(L0.z, L0.w), w2);
            fma2(acc[2], pack2(L1.x, L1.y), w2);
            fma2(acc[3], pack2(L1.z, L1.w), w2);
            fma2(acc[4], pack2(L2.x, L2.y), w2);
            fma2(acc[5], pack2(L2.z, L2.w), w2);
            fma2(acc[6], pack2(L3.x, L3.y), w2);
            fma2(acc[7], pack2(L3.z, L3.w), w2);
            if (doU) u += sv[i] * wv;
        }
        unsigned long long d2 = 0ull;
        #pragma unroll
        for (int q = 0; q < 8; ++q) fma2(d2, acc[q], acc[q]);
        float2 dd = unpack2(d2);
        int c = 32 * g + lane;
        atomicAdd(&sD[c], dd.x + dd.y);
        if (doU) sU[c] = u;
    }
    __syncthreads();

    for (int c = tid; c < C; c += 256) {
        g_D[s * A_DIM + c] = sD[c];
        g_U[s * A_DIM + c] = sU[c];
    }
}

// ---------------- class-grouped solves: score[n][k] = dist + logdet ---------
__global__ __launch_bounds__(256, 3)
void k_solve(const float* __restrict__ F, const float* __restrict__ mu, int K) {
    extern __shared__ float sh[];
    float* sLT = sh;                       // 128 * 132
    float* srd = sLT + A_DIM * PITCH;      // 128
    const int s = blockIdx.x;
    const int cls = s / K;
    const int kk = s - cls * K;
    const int tid = threadIdx.x, wid = tid >> 5, lane = tid & 31;

    {
        const float4* LT4 = reinterpret_cast<const float4*>(g_LT + (size_t)s * (A_DIM * A_DIM));
        for (int idx = tid; idx < A_DIM * 32; idx += 256) {
            int j = idx >> 5, f = idx & 31;
            *reinterpret_cast<float4*>(&sLT[j * PITCH + 4 * f]) = LT4[idx];
        }
        if (tid < A_DIM) srd[tid] = g_rdiag[s * A_DIM + tid];
    }
    __syncthreads();

    const int cnt = g_ccount[cls];
    const float logd = g_logdet[s];
    const float4* F4 = reinterpret_cast<const float4*>(F);
    const float4 mv = reinterpret_cast<const float4*>(mu)[(size_t)s * 32 + lane];

    for (int m = wid; m < cnt; m += 16) {
        const int nA = g_clist[(size_t)cls * MAX_N + m];
        const int mB = m + 8;
        const bool hasB = (mB < cnt);
        const int nB = hasB ? g_clist[(size_t)cls * MAX_N + mB] : nA;

        float4 fA = F4[(size_t)nA * 32 + lane];
        float4 fB = F4[(size_t)nB * 32 + lane];
        float a0 = fA.x - mv.x, a1 = fA.y - mv.y, a2 = fA.z - mv.z, a3 = fA.w - mv.w;
        float b0 = fB.x - mv.x, b1 = fB.y - mv.y, b2 = fB.z - mv.z, b3 = fB.w - mv.w;
        float dA = 0.0f, dB = 0.0f;

        #pragma unroll 4
        for (int j = 0; j < A_DIM; ++j) {
            float4 col = *reinterpret_cast<const float4*>(&sLT[j * PITCH + 4 * lane]);
            float rdj = srd[j];
            int owner = j >> 2, q = j & 3;
            float qa = (q == 0) ? a0 : (q == 1) ? a1 : (q == 2) ? a2 : a3;
            float qb = (q == 0) ? b0 : (q == 1) ? b1 : (q == 2) ? b2 : b3;
            float za = __shfl_sync(0xffffffffu, qa, owner) * rdj;
            float zb = __shfl_sync(0xffffffffu, qb, owner) * rdj;
            dA += za * za;            dB += zb * zb;
            a0 -= col.x * za;         b0 -= col.x * zb;
            a1 -= col.y * za;         b1 -= col.y * zb;
            a2 -= col.z * za;         b2 -= col.z * zb;
            a3 -= col.w * za;         b3 -= col.w * zb;
        }
        if (lane == 0) {
            g_score[nA * 8 + kk] = dA + logd;
            if (hasB) g_score[nB * 8 + kk] = dB + logd;
        }
    }
}

// ---------------- fused y = F W^T + b, argmin, aug, log-softmax, loss --------
__global__ void k_yloss(const float* __restrict__ F, const float* __restrict__ W,
                        const float* __restrict__ bias, const float* __restrict__ ratioPtr,
                        float* __restrict__ yout, float* __restrict__ lossout,
                        int N, int C, int K, int writeLoss) {
    extern __shared__ float sh[];
    const int NB = 16;
    float* sWT = sh;
    float* sF  = sWT + A_DIM * C;
    float* sY  = sF + NB * A_DIM;
    float* sB  = sY + NB * C;
    const int tid = threadIdx.x;
    const int n0 = blockIdx.x * NB;

    for (int idx = tid; idx < C * A_DIM; idx += 256) {
        int c = idx >> 7, aa = idx & 127;
        sWT[aa * C + c] = W[idx];
    }
    for (int idx = tid; idx < NB * A_DIM; idx += 256) {
        int nl = idx >> 7;
        int n = n0 + nl;
        sF[idx] = (n < N) ? F[(size_t)n * A_DIM + (idx & 127)] : 0.0f;
    }
    for (int c = tid; c < C; c += 256) sB[c] = bias[c];
    __syncthreads();

    const int warp = tid >> 5, lane = tid & 31;
    const int nchunk = (C + 31) >> 5;

    for (int task = warp; task < NB * nchunk; task += 8) {
        int nl = task / nchunk;
        int c = (task - nl * nchunk) * 32 + lane;
        int n = n0 + nl;
        if (c < C && n < N) {
            float acc = sB[c];
            const float* f = sF + nl * A_DIM;
            #pragma unroll 8
            for (int aa = 0; aa < A_DIM; ++aa) acc += f[aa] * sWT[aa * C + c];
            sY[nl * C + c] = acc;
            yout[(size_t)n * C + c] = acc;
        }
    }
    __syncthreads();

    const float hr = 0.5f * ratioPtr[0];
    for (int nl = warp; nl < NB; nl += 8) {
        int n = n0 + nl;
        if (n >= N) continue;
        int l = g_labels[n];
        const float* sc = g_score + n * 8;
        int k = 0;
        float best = sc[0];
        for (int kk = 1; kk < K; ++kk) {
            float v = sc[kk];
            if (v < best) { best = v; k = kk; }
        }
        int s = l * K + k;
        const float* Dp = g_D + s * A_DIM;
        const float* Up = g_U + s * A_DIM;
        float ul = Up[l];
        float mymax = -INFINITY;
        float augv[8];
        for (int m = 0; m < nchunk; ++m) {
            int c = lane + 32 * m;
            float v = -INFINITY;
            if (c < C) v = sY[nl * C + c] + hr * (Dp[c] - 2.0f * Up[c] + ul);
            augv[m] = v;
            mymax = fmaxf(mymax, v);
        }
        #pragma unroll
        for (int o = 16; o; o >>= 1) mymax = fmaxf(mymax, __shfl_xor_sync(0xffffffffu, mymax, o));
        float sum = 0.0f;
        for (int m = 0; m < nchunk; ++m) {
            int c = lane + 32 * m;
            if (c < C) sum += expf(augv[m] - mymax);
        }
        #pragma unroll
        for (int o = 16; o; o >>= 1) sum += __shfl_xor_sync(0xffffffffu, sum, o);
        if (lane == 0 && writeLoss) {
            float lse = mymax + logf(sum);
            float aug_l = sY[nl * C + l] + hr * (Dp[l] - Up[l]);
            atomicAdd(lossout, (lse - aug_l) / (float)N);
        }
    }
}

// ---------------- launch -----------------------------------------------------
extern "C" void kernel_launch(void* const* d_in, const int* in_sizes, int n_in,
                              void* d_out, int out_size) {
    const float* F     = (const float*)d_in[0];
    const float* W     = (const float*)d_in[1];
    const float* bias  = (const float*)d_in[2];
    const float* mu    = (const float*)d_in[4];
    const float* sigma = (const float*)d_in[5];
    const int*   lraw  = (const int*)d_in[6];
    const float* ratio = (const float*)d_in[7];

    const int C = in_sizes[2];
    const int K = in_sizes[3] / C;
    const int Ad = in_sizes[1] / C;
    const int N = in_sizes[0] / Ad;
    const int S = C * K;

    float* out = (float*)d_out;
    const int yoff = out_size - N * C;
    const int writeLoss = (yoff >= 1) ? 1 : 0;
    float* yout = out + (yoff > 0 ? yoff : 0);

    const int smem_fused = (A_DIM * PITCH + A_DIM * 33 + 6 * A_DIM) * 4;   // 87552
    const int smem_solve = (A_DIM * PITCH + A_DIM) * 4;                    // 68096
    const int smem_yl    = (A_DIM * C + 16 * A_DIM + 16 * C + C) * 4;

    cudaFuncSetAttribute(k_fused, cudaFuncAttributeMaxDynamicSharedMemorySize, smem_fused);
    cudaFuncSetAttribute(k_solve, cudaFuncAttributeMaxDynamicSharedMemorySize, smem_solve);
    cudaFuncSetAttribute(k_yloss, cudaFuncAttributeMaxDynamicSharedMemorySize, smem_yl);

    k_init<<<1, 32>>>(out, writeLoss);
    k_labels<<<1, 256>>>(lraw, N, C);
    k_fused<<<S, 256, smem_fused>>>(sigma, W, C, K);
    k_solve<<<S, 256, smem_solve>>>(F, mu, K);
    k_yloss<<<(N + 15) / 16, 256, smem_yl>>>(F, W, bias, ratio, yout, out, N, C, K, writeLoss);
}

// round 5
// speedup vs baseline: 2.9208x; 1.1044x over previous
#include <cuda_runtime.h>
#include <math.h>

// ISDALoss_EM on GB300 — round 5: fully fused per-sigma kernel (no L round trip).
#define A_DIM 128
#define PITCH 132
#define MAX_S 512
#define MAX_N 4096
#define MAX_C 128

__device__ float g_D[MAX_S * A_DIM];
__device__ float g_U[MAX_S * A_DIM];
__device__ float g_score[MAX_N * 8];
__device__ int   g_labels[MAX_N];
__device__ int   g_ccount[MAX_C];
__device__ int   g_clist[(size_t)MAX_C * MAX_N];

__device__ __forceinline__ void fma2(unsigned long long& d, unsigned long long a,
                                     unsigned long long b) {
    asm("fma.rn.f32x2 %0, %1, %2, %0;" : "+l"(d) : "l"(a), "l"(b));
}
__device__ __forceinline__ unsigned long long pack2(float lo, float hi) {
    unsigned long long r;
    asm("mov.b64 %0, {%1,%2};" : "=l"(r) : "f"(lo), "f"(hi));
    return r;
}
__device__ __forceinline__ float2 unpack2(unsigned long long v) {
    float2 f;
    asm("mov.b64 {%0,%1}, %2;" : "=f"(f.x), "=f"(f.y) : "l"(v));
    return f;
}

__global__ void k_init(float* out, int writeLoss) {
    if (writeLoss && threadIdx.x == 0 && blockIdx.x == 0) out[0] = 0.0f;
}

// labels: dtype detect + convert + per-class sample lists (single block)
__global__ void k_labels(const int* __restrict__ raw, int n, int C) {
    __shared__ int odd_nz;
    const int tid = threadIdx.x;
    if (tid == 0) odd_nz = 0;
    if (tid < MAX_C) g_ccount[tid] = 0;
    __syncthreads();
    for (int i = tid; i < n / 2; i += blockDim.x)
        if (raw[2 * i + 1] != 0) atomicOr(&odd_nz, 1);
    __syncthreads();
    if (odd_nz == 0) {
        for (int i = tid; i < n; i += blockDim.x) g_labels[i] = raw[2 * i];
    } else {
        for (int i = tid; i < n; i += blockDim.x) g_labels[i] = raw[i];
    }
    __syncthreads();
    for (int i = tid; i < n; i += blockDim.x) {
        int c = g_labels[i];
        int p = atomicAdd(&g_ccount[c], 1);
        g_clist[(size_t)c * MAX_N + p] = i;
    }
}

// ---- fused: v, blocked Cholesky, D/U, in-smem transpose, class solves -------
__global__ __launch_bounds__(256, 2)
void k_fused(const float* __restrict__ sigma, const float* __restrict__ W,
             const float* __restrict__ F, const float* __restrict__ mu,
             int C, int K) {
    extern __shared__ float sh[];
    float* sA  = sh;                       // 128 * 132
    float* sW  = sA + A_DIM * PITCH;       // 128 * 33
    float* swl = sW + A_DIM * 33;          // 128
    float* sv  = swl + A_DIM;              // 128
    float* srd = sv + A_DIM;               // 128
    float* sdg = srd + A_DIM;              // 128
    float* sD  = sdg + A_DIM;              // 128
    float* sU  = sD + A_DIM;               // 128
    __shared__ float slogdet;

    const int s = blockIdx.x;
    const int cls = s / K;
    const int kk = s - cls * K;
    const int tid = threadIdx.x;
    const int wid = tid >> 5, lane = tid & 31;

    // ---- load Sigma (float4, coalesced), w_l; zero sD ----
    {
        const float4* src4 = reinterpret_cast<const float4*>(sigma + (size_t)s * A_DIM * A_DIM);
        for (int idx = tid; idx < A_DIM * 32; idx += 256) {
            int i = idx >> 5, f = idx & 31;
            *reinterpret_cast<float4*>(&sA[i * PITCH + 4 * f]) = src4[idx];
        }
        if (tid < A_DIM) { swl[tid] = W[cls * A_DIM + tid]; sD[tid] = 0.0f; }
    }
    __syncthreads();

    // ---- v = Sigma @ w_l (before factorization) ----
    if (tid < A_DIM) {
        float acc = 0.0f;
        #pragma unroll 8
        for (int b = 0; b < A_DIM; ++b) acc += sA[b * PITCH + tid] * swl[b];
        sv[tid] = acc;
    }
    __syncthreads();

    // ---- blocked Cholesky (NB = 32) ----
    for (int kb = 0; kb < A_DIM; kb += 32) {
        if (wid == 0) {
            float m[32];
            float* row = &sA[(kb + lane) * PITCH + kb];
            #pragma unroll
            for (int c = 0; c < 32; ++c) m[c] = row[c];
            #pragma unroll
            for (int j = 0; j < 32; ++j) {
                float dj = __shfl_sync(0xffffffffu, m[j], j);
                float l = m[j] * rsqrtf(dj);
                m[j] = l;
                #pragma unroll
                for (int p = j + 1; p < 32; ++p)
                    m[p] -= l * __shfl_sync(0xffffffffu, l, p);
            }
            #pragma unroll
            for (int c = 0; c < 32; ++c)
                if (c <= lane) row[c] = m[c];
            srd[kb + lane] = 1.0f / m[lane];
            sdg[kb + lane] = m[lane];
        }
        __syncthreads();

        const int R = A_DIM - kb - 32;
        if (R > 0) {
            if (tid < R) {
                const int row = kb + 32 + tid;
                float* pr = &sA[row * PITCH + kb];
                const float* pd = &sA[kb * PITCH + kb];
                float x[32];
                #pragma unroll
                for (int c = 0; c < 32; ++c) x[c] = pr[c];
                #pragma unroll
                for (int j = 0; j < 32; ++j) {
                    float a = x[j];
                    #pragma unroll
                    for (int p = 0; p < j; ++p) a -= x[p] * pd[j * PITCH + p];
                    x[j] = a * srd[kb + j];
                }
                #pragma unroll
                for (int c = 0; c < 32; ++c) pr[c] = x[c];
            }
            __syncthreads();

            const int nb = R >> 5;
            const int ntask = nb * (nb + 1);
            for (int task = wid; task < ntask; task += 8) {
                int b = 0, t = task;
                while (t >= 2 * b + 2) { t -= 2 * b + 2; ++b; }
                const int i  = kb + 32 + 32 * b + lane;
                const int j0 = kb + 32 + 16 * t;
                unsigned long long acc[16];
                #pragma unroll
                for (int q = 0; q < 16; ++q) acc[q] = 0ull;
                const float* pa = &sA[i * PITCH + kb];
                #pragma unroll
                for (int k = 0; k < 32; k += 4) {
                    ulonglong2 av = *reinterpret_cast<const ulonglong2*>(pa + k);
                    #pragma unroll
                    for (int q = 0; q < 16; ++q) {
                        ulonglong2 bv = *reinterpret_cast<const ulonglong2*>(
                            &sA[(j0 + q) * PITCH + kb + k]);
                        fma2(acc[q], av.x, bv.x);
                        fma2(acc[q], av.y, bv.y);
                    }
                }
                #pragma unroll
                for (int q = 0; q < 16; ++q) {
                    int col = j0 + q;
                    if (col <= i) {
                        float2 f = unpack2(acc[q]);
                        sA[i * PITCH + col] -= f.x + f.y;
                    }
                }
            }
            __syncthreads();
        }
    }

    // ---- zero upper triangle; logdet ----
    for (int idx = tid; idx < A_DIM * A_DIM; idx += 256) {
        int j = idx >> 7, i = idx & 127;
        if (i < j) sA[i * PITCH + j] = 0.0f;
    }
    if (tid < 32) {
        float v = logf(sdg[tid]) + logf(sdg[tid + 32]) +
                  logf(sdg[tid + 64]) + logf(sdg[tid + 96]);
        #pragma unroll
        for (int o = 16; o; o >>= 1) v += __shfl_xor_sync(0xffffffffu, v, o);
        if (tid == 0) slogdet = 2.0f * v;
    }

    // ---- D_c = ||L^T w_c||^2 (triangular, register-tiled), U_c = v . w_c ----
    for (int g = 0; g < 4; ++g) {
        __syncthreads();
        for (int idx = tid; idx < 32 * 32; idx += 256) {
            int cc = idx >> 5, f = idx & 31;
            int c = 32 * g + cc;
            float4 wv = (c < C) ? reinterpret_cast<const float4*>(W + (size_t)c * A_DIM)[f]
                                : make_float4(0.f, 0.f, 0.f, 0.f);
            sW[(4 * f + 0) * 33 + cc] = wv.x;
            sW[(4 * f + 1) * 33 + cc] = wv.y;
            sW[(4 * f + 2) * 33 + cc] = wv.z;
            sW[(4 * f + 3) * 33 + cc] = wv.w;
        }
        __syncthreads();

        const int t = (g & 1) ? (7 - wid) : wid;
        const int j0 = 16 * t;
        unsigned long long acc[8];
        #pragma unroll
        for (int q = 0; q < 8; ++q) acc[q] = 0ull;
        float u = 0.0f;
        const bool doU = (t == 0);

        for (int i = j0; i < A_DIM; ++i) {
            const float* Lr = &sA[i * PITCH + j0];
            float4 L0 = *reinterpret_cast<const float4*>(Lr);
            float4 L1 = *reinterpret_cast<const float4*>(Lr + 4);
            float4 L2 = *reinterpret_cast<const float4*>(Lr + 8);
            float4 L3 = *reinterpret_cast<const float4*>(Lr + 12);
            float wv = sW[i * 33 + lane];
            unsigned long long w2 = pack2(wv, wv);
            fma2(acc[0], pack2(L0.x, L0.y), w2);
            fma2(acc[1], pack2(L0.z, L0.w), w2);
            fma2(acc[2], pack2(L1.x, L1.y), w2);
            fma2(acc[3], pack2(L1.z, L1.w), w2);
            fma2(acc[4], pack2(L2.x, L2.y), w2);
            fma2(acc[5], pack2(L2.z, L2.w), w2);
            fma2(acc[6], pack2(L3.x, L3.y), w2);
            fma2(acc[7], pack2(L3.z, L3.w), w2);
            if (doU) u += sv[i] * wv;
        }
        unsigned long long d2 = 0ull;
        #pragma unroll
        for (int q = 0; q < 8; ++q) fma2(d2, acc[q], acc[q]);
        float2 dd = unpack2(d2);
        int c = 32 * g + lane;
        atomicAdd(&sD[c], dd.x + dd.y);
        if (doU) sU[c] = u;
    }
    __syncthreads();

    for (int c = tid; c < C; c += 256) {
        g_D[s * A_DIM + c] = sD[c];
        g_U[s * A_DIM + c] = sU[c];
    }

    // ---- in-place transpose: sA[j][i] = L[i][j] (i>j), zero the old lower ----
    for (int idx = tid; idx < A_DIM * A_DIM; idx += 256) {
        int i = idx >> 7, j = idx & 127;
        if (i > j) {
            float v = sA[i * PITCH + j];
            sA[j * PITCH + i] = v;
            sA[i * PITCH + j] = 0.0f;
        }
    }
    __syncthreads();

    // ---- class-grouped solves: score = dist + logdet, 4 samples per warp ----
    const int cnt = g_ccount[cls];
    const float logd = slogdet;
    const float4* F4 = reinterpret_cast<const float4*>(F);
    const float4 mv = reinterpret_cast<const float4*>(mu)[(size_t)s * 32 + lane];

    for (int m0 = wid * 4; m0 < cnt; m0 += 32) {
        int n[4];
        bool has[4];
        #pragma unroll
        for (int r = 0; r < 4; ++r) {
            has[r] = (m0 + r) < cnt;
            n[r] = g_clist[(size_t)cls * MAX_N + (has[r] ? (m0 + r) : m0)];
        }
        float d[4][4], dist[4];
        #pragma unroll
        for (int r = 0; r < 4; ++r) {
            float4 fv = F4[(size_t)n[r] * 32 + lane];
            d[r][0] = fv.x - mv.x; d[r][1] = fv.y - mv.y;
            d[r][2] = fv.z - mv.z; d[r][3] = fv.w - mv.w;
            dist[r] = 0.0f;
        }
        #pragma unroll 4
        for (int j = 0; j < A_DIM; ++j) {
            float4 col = *reinterpret_cast<const float4*>(&sA[j * PITCH + 4 * lane]);
            float rdj = srd[j];
            int owner = j >> 2, q = j & 3;
            #pragma unroll
            for (int r = 0; r < 4; ++r) {
                float dq = (q == 0) ? d[r][0] : (q == 1) ? d[r][1]
                         : (q == 2) ? d[r][2] : d[r][3];
                float z = __shfl_sync(0xffffffffu, dq, owner) * rdj;
                dist[r] += z * z;
                d[r][0] -= col.x * z;
                d[r][1] -= col.y * z;
                d[r][2] -= col.z * z;
                d[r][3] -= col.w * z;
            }
        }
        if (lane == 0) {
            #pragma unroll
            for (int r = 0; r < 4; ++r)
                if (has[r]) g_score[n[r] * 8 + kk] = dist[r] + logd;
        }
    }
}

// ---------------- fused y = F W^T + b, argmin, aug, log-softmax, loss --------
__global__ void k_yloss(const float* __restrict__ F, const float* __restrict__ W,
                        const float* __restrict__ bias, const float* __restrict__ ratioPtr,
                        float* __restrict__ yout, float* __restrict__ lossout,
                        int N, int C, int K, int writeLoss) {
    extern __shared__ float sh[];
    const int NB = 16;
    float* sWT = sh;
    float* sF  = sWT + A_DIM * C;
    float* sY  = sF + NB * A_DIM;
    float* sB  = sY + NB * C;
    const int tid = threadIdx.x;
    const int n0 = blockIdx.x * NB;

    for (int idx = tid; idx < C * A_DIM; idx += 256) {
        int c = idx >> 7, aa = idx & 127;
        sWT[aa * C + c] = W[idx];
    }
    for (int idx = tid; idx < NB * A_DIM; idx += 256) {
        int nl = idx >> 7;
        int n = n0 + nl;
        sF[idx] = (n < N) ? F[(size_t)n * A_DIM + (idx & 127)] : 0.0f;
    }
    for (int c = tid; c < C; c += 256) sB[c] = bias[c];
    __syncthreads();

    const int warp = tid >> 5, lane = tid & 31;
    const int nchunk = (C + 31) >> 5;

    for (int task = warp; task < NB * nchunk; task += 8) {
        int nl = task / nchunk;
        int c = (task - nl * nchunk) * 32 + lane;
        int n = n0 + nl;
        if (c < C && n < N) {
            float acc = sB[c];
            const float* f = sF + nl * A_DIM;
            #pragma unroll
            for (int aa = 0; aa < A_DIM; aa += 4) {
                float4 fv = *reinterpret_cast<const float4*>(f + aa);
                acc += fv.x * sWT[aa * C + c];
                acc += fv.y * sWT[(aa + 1) * C + c];
                acc += fv.z * sWT[(aa + 2) * C + c];
                acc += fv.w * sWT[(aa + 3) * C + c];
            }
            sY[nl * C + c] = acc;
            yout[(size_t)n * C + c] = acc;
        }
    }
    __syncthreads();

    const float hr = 0.5f * ratioPtr[0];
    for (int nl = warp; nl < NB; nl += 8) {
        int n = n0 + nl;
        if (n >= N) continue;
        int l = g_labels[n];
        const float* sc = g_score + n * 8;
        int k = 0;
        float best = sc[0];
        for (int kkk = 1; kkk < K; ++kkk) {
            float v = sc[kkk];
            if (v < best) { best = v; k = kkk; }
        }
        int s = l * K + k;
        const float* Dp = g_D + s * A_DIM;
        const float* Up = g_U + s * A_DIM;
        float ul = Up[l];
        float mymax = -INFINITY;
        float augv[8];
        for (int m = 0; m < nchunk; ++m) {
            int c = lane + 32 * m;
            float v = -INFINITY;
            if (c < C) v = sY[nl * C + c] + hr * (Dp[c] - 2.0f * Up[c] + ul);
            augv[m] = v;
            mymax = fmaxf(mymax, v);
        }
        #pragma unroll
        for (int o = 16; o; o >>= 1) mymax = fmaxf(mymax, __shfl_xor_sync(0xffffffffu, mymax, o));
        float sum = 0.0f;
        for (int m = 0; m < nchunk; ++m) {
            int c = lane + 32 * m;
            if (c < C) sum += expf(augv[m] - mymax);
        }
        #pragma unroll
        for (int o = 16; o; o >>= 1) sum += __shfl_xor_sync(0xffffffffu, sum, o);
        if (lane == 0 && writeLoss) {
            float lse = mymax + logf(sum);
            float aug_l = sY[nl * C + l] + hr * (Dp[l] - Up[l]);
            atomicAdd(lossout, (lse - aug_l) / (float)N);
        }
    }
}

// ---------------- launch -----------------------------------------------------
extern "C" void kernel_launch(void* const* d_in, const int* in_sizes, int n_in,
                              void* d_out, int out_size) {
    const float* F     = (const float*)d_in[0];
    const float* W     = (const float*)d_in[1];
    const float* bias  = (const float*)d_in[2];
    const float* mu    = (const float*)d_in[4];
    const float* sigma = (const float*)d_in[5];
    const int*   lraw  = (const int*)d_in[6];
    const float* ratio = (const float*)d_in[7];

    const int C = in_sizes[2];
    const int K = in_sizes[3] / C;
    const int Ad = in_sizes[1] / C;
    const int N = in_sizes[0] / Ad;
    const int S = C * K;

    float* out = (float*)d_out;
    const int yoff = out_size - N * C;
    const int writeLoss = (yoff >= 1) ? 1 : 0;
    float* yout = out + (yoff > 0 ? yoff : 0);

    const int smem_fused = (A_DIM * PITCH + A_DIM * 33 + 6 * A_DIM) * 4;   // 87552
    const int smem_yl    = (A_DIM * C + 16 * A_DIM + 16 * C + C) * 4;

    cudaFuncSetAttribute(k_fused, cudaFuncAttributeMaxDynamicSharedMemorySize, smem_fused);
    cudaFuncSetAttribute(k_yloss, cudaFuncAttributeMaxDynamicSharedMemorySize, smem_yl);

    k_init<<<1, 32>>>(out, writeLoss);
    k_labels<<<1, 256>>>(lraw, N, C);
    k_fused<<<S, 256, smem_fused>>>(sigma, W, F, mu, C, K);
    k_yloss<<<(N + 15) / 16, 256, smem_yl>>>(F, W, bias, ratio, yout, out, N, C, K, writeLoss);
}